// round 9
// baseline (speedup 1.0000x reference)
#include <cuda_runtime.h>
#include <cuda_bf16.h>
#include <cuda_fp16.h>
#include <cstdint>

typedef unsigned long long ull;

constexpr int T_ = 64, B_ = 64, N_ = 64, D_ = 128, HID_ = 256;
constexpr int BND = B_ * N_ * D_;                      // 524288
constexpr size_t TOT  = (size_t)T_ * BND;              // 33554432
constexpr size_t TOTH = (size_t)T_ * B_ * N_ * HID_;   // 67108864

// -------- scratch (no allocations allowed) --------
__device__ float g_M[64 * 64];
__device__ ull   g_Mp[32 * 64];
__device__ __half g_xs[2][TOT];     // x splits (fp16 hi/lo)
__device__ __half g_ms[2][TOT];     // mlp splits
__device__ __half g_os[2][TOT];     // o splits (exact)
__device__ __half g_xgs[2][TOT];    // xg splits
__device__ float  g_xg[TOT];        // xg fp32 (final gating)
__device__ __half g_q[TOT];         // binary spikes (exact fp16)
__device__ __half g_k[TOT];
__device__ __half g_v[TOT];
__device__ __half g_h1[TOTH];
__device__ __half g_wsp[7][2 * 128 * 256];   // weight splits [2][128n][K]

// -------- helpers --------
__device__ __forceinline__ void ffma2(ull& d, ull a, ull b) {
    asm("fma.rn.f32x2 %0, %1, %2, %0;" : "+l"(d) : "l"(a), "l"(b));
}
__device__ __forceinline__ ull dup2(float x) {
    ull r; unsigned u = __float_as_uint(x);
    asm("mov.b64 %0, {%1, %1};" : "=l"(r) : "r"(u));
    return r;
}
__device__ __forceinline__ ull pack2(float lo, float hi) {
    ull r;
    asm("mov.b64 %0, {%1, %2};" : "=l"(r) : "r"(__float_as_uint(lo)), "r"(__float_as_uint(hi)));
    return r;
}
__device__ __forceinline__ uint32_t smem_u32(const void* p) {
    uint32_t a;
    asm("{ .reg .u64 t; cvta.to.shared.u64 t, %1; cvt.u32.u64 %0, t; }" : "=r"(a) : "l"(p));
    return a;
}
__device__ __forceinline__ uint32_t sw128(uint32_t off) { return off ^ ((off >> 3) & 0x70); }
__device__ __forceinline__ void ldsm4(uint32_t* r, uint32_t addr) {
    asm volatile("ldmatrix.sync.aligned.m8n8.x4.shared.b16 {%0,%1,%2,%3}, [%4];"
                 : "=r"(r[0]), "=r"(r[1]), "=r"(r[2]), "=r"(r[3]) : "r"(addr));
}
__device__ __forceinline__ void mma16816(float* d, const uint32_t* a, uint32_t b0, uint32_t b1) {
    asm volatile(
        "mma.sync.aligned.m16n8k16.row.col.f32.f16.f16.f32 "
        "{%0,%1,%2,%3}, {%4,%5,%6,%7}, {%8,%9}, {%0,%1,%2,%3};"
        : "+f"(d[0]), "+f"(d[1]), "+f"(d[2]), "+f"(d[3])
        : "r"(a[0]), "r"(a[1]), "r"(a[2]), "r"(a[3]), "r"(b0), "r"(b1));
}
__device__ __forceinline__ uint32_t h2x(float lo, float hi) {
    uint32_t r;
    asm("cvt.rn.f16x2.f32 %0, %1, %2;" : "=r"(r) : "f"(hi), "f"(lo));
    return r;
}
__device__ __forceinline__ void cpa16(uint32_t dst, const void* src) {
    asm volatile("cp.async.cg.shared.global [%0], [%1], 16;" :: "r"(dst), "l"(src));
}
__device__ __forceinline__ void cpa_commit() { asm volatile("cp.async.commit_group;"); }
template <int NWAIT>
__device__ __forceinline__ void cpa_wait() {
    asm volatile("cp.async.wait_group %0;" :: "n"(NWAIT));
}

// =====================================================================
// DCT operator + packed form
// =====================================================================
__global__ void k_dct() {
    int t = blockIdx.x, s = threadIdx.x;
    const double PI = 3.141592653589793238462643383279502884;
    double acc = 0.0;
    for (int kk = 0; kk < 16; kk++) {
        double scale = (kk == 0) ? sqrt(1.0 / 64.0) : sqrt(2.0 / 64.0);
        float ct = (float)(cos(PI * (t + 0.5) * kk / 64.0) * scale);
        float cs = (float)(cos(PI * (s + 0.5) * kk / 64.0) * scale);
        acc += (double)ct * (double)cs;
    }
    g_M[t * 64 + s] = (float)acc;
}
__global__ void k_pack() {
    int t2 = blockIdx.x, s = threadIdx.x;
    g_Mp[t2 * 64 + s] = pack2(g_M[(2 * t2) * 64 + s], g_M[(2 * t2 + 1) * 64 + s]);
}

// =====================================================================
// Merged weight split (2-way fp16)
// =====================================================================
__global__ void k_wsplit_all(const float* __restrict__ Wq, const float* __restrict__ Wk,
                             const float* __restrict__ Wv, const float* __restrict__ Wo,
                             const float* __restrict__ W1, const float* __restrict__ W2) {
    int bi = blockIdx.x;
    int tile, ob;
    if (bi < 384) { tile = bi >> 6; ob = bi & 63; }
    else { tile = 6; ob = bi - 384; }
    const float* W; int ldw, col0, K;
    switch (tile) {
        case 0: W = Wq; ldw = 128; col0 = 0;   K = 128; break;
        case 1: W = Wk; ldw = 128; col0 = 0;   K = 128; break;
        case 2: W = Wv; ldw = 128; col0 = 0;   K = 128; break;
        case 3: W = Wo; ldw = 128; col0 = 0;   K = 128; break;
        case 4: W = W1; ldw = 256; col0 = 0;   K = 128; break;
        case 5: W = W1; ldw = 256; col0 = 128; K = 128; break;
        default: W = W2; ldw = 128; col0 = 0;  K = 256; break;
    }
    __half* out = &g_wsp[tile][0];
    int idx = ob * 256 + threadIdx.x;
    int n = idx / K, k = idx - n * K;
    float w = W[(size_t)k * ldw + col0 + n];
    __half hi = __float2half_rn(w);
    float r1 = __fsub_rn(w, __half2float(hi));
    out[(size_t)(0 * 128 + n) * K + k] = hi;
    out[(size_t)(1 * 128 + n) * K + k] = __float2half_rn(r1);
}

// =====================================================================
// x -> 2 fp16 splits, pure stream
// =====================================================================
__global__ void __launch_bounds__(256) k_xsplit(const float* __restrict__ x) {
    size_t i0 = ((size_t)blockIdx.x * 256 + threadIdx.x) * 8;
    const size_t step = (size_t)gridDim.x * 256 * 8;
    for (size_t i = i0; i < TOT; i += step) {
        float4 f0 = *reinterpret_cast<const float4*>(&x[i]);
        float4 f1 = *reinterpret_cast<const float4*>(&x[i + 4]);
        float a[8] = {f0.x, f0.y, f0.z, f0.w, f1.x, f1.y, f1.z, f1.w};
        uint32_t hp[4], lp[4];
#pragma unroll
        for (int e = 0; e < 4; e++) {
            float v0 = a[2 * e], v1 = a[2 * e + 1];
            __half h0 = __float2half_rn(v0), h1 = __float2half_rn(v1);
            float r0 = __fsub_rn(v0, __half2float(h0));
            float r1 = __fsub_rn(v1, __half2float(h1));
            hp[e] = (uint32_t)*(uint16_t*)&h0 | ((uint32_t)*(uint16_t*)&h1 << 16);
            lp[e] = h2x(r0, r1);
        }
        *reinterpret_cast<uint4*>(&g_xs[0][i]) = *reinterpret_cast<uint4*>(hp);
        *reinterpret_cast<uint4*>(&g_xs[1][i]) = *reinterpret_cast<uint4*>(lp);
    }
}

// =====================================================================
// Memory mix + temporal lowpass; emits 2 fp16 splits
// =====================================================================
__global__ void __launch_bounds__(256) k_mix(const float* __restrict__ x,
                                             const float* __restrict__ mx) {
    __shared__ float s_p[64 * 128];
    __shared__ ull  s_Mp[32 * 64];
    const int bn = blockIdx.x;
    const int b = bn >> 6, n = bn & 63;
    const int tid = threadIdx.x;

    for (int i = tid; i < 2048; i += 256) s_Mp[i] = g_Mp[i];

    const float* xb = x + (size_t)(b * N_ + n) * D_;
    const float* mb = mx + ((size_t)(n * B_ + b) * T_) * D_;
    for (int i = tid; i < 8192; i += 256) {
        float mv = mb[i];
        float mv2 = __fadd_rn(__fmul_rn(0.05f, mv), __fmul_rn(0.95f, mv));
        s_p[i] = __fmul_rn(xb[(size_t)(i >> 7) * BND + (i & 127)], mv2);
    }
    __syncthreads();

    const int d = tid & 127;
    const int t2b = (tid >> 7) * 16;
    ull acc[16];
#pragma unroll
    for (int j = 0; j < 16; j++) acc[j] = 0ull;
    for (int s = 0; s < 64; s++) {
        ull cp = dup2(s_p[s * 128 + d]);
#pragma unroll
        for (int j = 0; j < 16; j++) ffma2(acc[j], s_Mp[(t2b + j) * 64 + s], cp);
    }
#pragma unroll
    for (int j = 0; j < 16; j++) {
        float2 f = *reinterpret_cast<float2*>(&acc[j]);
#pragma unroll
        for (int e = 0; e < 2; e++) {
            float v = (e == 0) ? f.x : f.y;
            size_t oi = ((size_t)(2 * (t2b + j) + e) * 4096 + bn) * 128 + d;
            __half hi = __float2half_rn(v);
            float r1 = __fsub_rn(v, __half2float(hi));
            g_ms[0][oi] = hi;
            g_ms[1][oi] = __float2half_rn(r1);
        }
    }
}

// =====================================================================
// Double-buffered fp16 tensor-core GEMM + fused LIF. 512 threads.
// 2-split operands; passes: hh, hl, lh (NSPLITS=2) or h,l of B (NSPLITS=1).
// =====================================================================
constexpr int STG = 65536;                  // 64KB per stage (2 A + 2 B tiles)
constexpr int SGEMM = 1024 + 2 * STG;       // 132096
constexpr int PPAD = 130;

template <int KCHUNKS, int MODE, int NSPLITS, int NSEL>
__global__ void __launch_bounds__(512, 1) k_mmag(
    const __half* __restrict__ aspl, size_t asstride,
    const __half* __restrict__ wspA, const __half* __restrict__ wspB,
    void* __restrict__ outA, void* __restrict__ outB,
    int ldo, int ocolmul,
    const float* __restrict__ gx,
    __half* __restrict__ so0, __half* __restrict__ so1) {
    extern __shared__ __align__(16) char smem_raw[];
    const uint32_t sbase = smem_u32(smem_raw);
    float* s_pre = (float*)(smem_raw + 1024);
    const int sel = (NSEL == 2) ? (int)(blockIdx.x >> 11) : 0;
    const int bn0 = ((NSEL == 2) ? (blockIdx.x & 2047) : blockIdx.x) * 2;
    const __half* wsp = sel ? wspB : wspA;
    void* outp = sel ? outB : outA;
    const int ocol0 = ocolmul * sel;
    const int tid = threadIdx.x;
    const int wid = tid >> 5, lane = tid & 31;
    constexpr int KTOT = KCHUNKS * 128;
    constexpr int NST = KCHUNKS * 2;

    const int m_base = (wid & 3) * 32;
    const int n_base = (wid >> 2) * 32;
    const int sub = lane >> 3, lr = lane & 7;
    const int arow_off = (sub & 1) * 8 + lr;
    const int akc = (sub >> 1) * 8;
    const int brow_off = (sub >> 1) * 8 + lr;
    const int bkc = (sub & 1) * 8;

    auto load_stage = [&](int s) {
        const int ch = s >> 1, kh = s & 1;
        const uint32_t dst = sbase + 1024 + (s & 1) * STG;
        for (int u = tid; u < NSPLITS * 1024; u += 512) {
            int sp = u >> 10, r = u & 1023, m = r >> 3, g = r & 7;
            int t = m & 63, tile = m >> 6;
            const __half* src = aspl + (size_t)sp * asstride +
                ((size_t)t * 4096 + bn0 + tile) * KTOT + ch * 128 + kh * 64 + g * 8;
            cpa16(dst + sp * 16384 + sw128((m << 7) + (g << 4)), src);
        }
        for (int u = tid; u < 2048; u += 512) {
            int sp = u >> 10, r = u & 1023, n = r >> 3, g = r & 7;
            const __half* src =
                wsp + ((size_t)(sp * 128 + n) * KTOT + ch * 128 + kh * 64 + g * 8);
            cpa16(dst + 32768 + sp * 16384 + sw128((n << 7) + (g << 4)), src);
        }
        cpa_commit();
    };

    float acc[2][4][4];
#pragma unroll
    for (int i = 0; i < 2; i++)
#pragma unroll
        for (int j = 0; j < 4; j++)
#pragma unroll
            for (int e = 0; e < 4; e++) acc[i][j][e] = 0.f;

    load_stage(0);
    if (NST > 1) load_stage(1);

#pragma unroll
    for (int s = 0; s < NST; s++) {
        if (s + 1 < NST) cpa_wait<1>(); else cpa_wait<0>();
        __syncthreads();

        const uint32_t Abuf = sbase + 1024 + (s & 1) * STG;
        const uint32_t Bbuf = Abuf + 32768;
        const int NP = (NSPLITS == 2) ? 3 : 2;
        const int PAs[3] = {0, 0, 1};
        const int PBs[3] = {0, 1, 0};
        const int PB1[3] = {0, 1, 0};

        for (int p = 0; p < NP; p++) {
            int As = (NSPLITS == 1) ? 0 : PAs[p];
            int Bs = (NSPLITS == 1) ? PB1[p] : PBs[p];
            uint32_t Abase = Abuf + As * 16384;
            uint32_t Bbase = Bbuf + Bs * 16384;
#pragma unroll
            for (int ks = 0; ks < 4; ks++) {
                int k0 = ks * 16;
                uint32_t afr[2][4];
#pragma unroll
                for (int mf = 0; mf < 2; mf++)
                    ldsm4(afr[mf], Abase +
                          sw128(((m_base + mf * 16 + arow_off) << 7) + (k0 + akc) * 2));
                uint32_t bfr[2][4];
#pragma unroll
                for (int nf2 = 0; nf2 < 2; nf2++)
                    ldsm4(bfr[nf2], Bbase +
                          sw128(((n_base + nf2 * 16 + brow_off) << 7) + (k0 + bkc) * 2));
#pragma unroll
                for (int mf = 0; mf < 2; mf++)
#pragma unroll
                    for (int nf = 0; nf < 4; nf++)
                        mma16816(acc[mf][nf], afr[mf],
                                 bfr[nf >> 1][(nf & 1) * 2], bfr[nf >> 1][(nf & 1) * 2 + 1]);
            }
        }
        __syncthreads();
        if (s + 2 < NST) load_stage(s + 2);
    }

    // ---- store fragments to s_pre ----
    {
        const int qr = lane >> 2, qc = (lane & 3) * 2;
#pragma unroll
        for (int mf = 0; mf < 2; mf++)
#pragma unroll
            for (int nf = 0; nf < 4; nf++) {
                int row = m_base + mf * 16 + qr;
                int col = n_base + nf * 8 + qc;
                *reinterpret_cast<float2*>(&s_pre[row * PPAD + col]) =
                    make_float2(acc[mf][nf][0], acc[mf][nf][1]);
                *reinterpret_cast<float2*>(&s_pre[(row + 8) * PPAD + col]) =
                    make_float2(acc[mf][nf][2], acc[mf][nf][3]);
            }
    }
    __syncthreads();

    // ---- fused LIF scan (first 256 threads) ----
    if (tid < 256) {
        const int tile = tid >> 7, c = tid & 127;
        const int bn = bn0 + tile;
        float vmem = 0.f;
        const size_t ostride = (size_t)4096 * ldo;
        const size_t obase = (size_t)bn * ldo + ocol0 + c;
        const size_t gbase = (size_t)bn * 128 + c;
#pragma unroll 1
        for (int t = 0; t < 64; t++) {
            float p = s_pre[(tile * 64 + t) * PPAD + c];
            vmem = __fadd_rn(vmem, __fmul_rn(__fsub_rn(p, vmem), 0.5f));
            float spk = (vmem >= 1.0f) ? 1.0f : 0.0f;
            if (vmem >= 1.0f) vmem = 0.0f;
            size_t oi = obase + (size_t)t * ostride;
            if (MODE == 0) {
                ((__half*)outp)[oi] = __float2half_rn(spk);
            } else {
                float g = gx[gbase + (size_t)t * (size_t)BND];
                float val = __fmul_rn(g, __fsub_rn(1.0f, spk));
                ((float*)outp)[oi] = val;
                if (MODE == 1) {
                    __half hi = __float2half_rn(val);
                    float r1 = __fsub_rn(val, __half2float(hi));
                    so0[oi] = hi;
                    so1[oi] = __float2half_rn(r1);
                }
            }
        }
    }
}

// =====================================================================
// Attention via tensor cores (exact fp16 in/out), emits o splits.
// =====================================================================
constexpr int ATT_Q = 0, ATT_K = 16384, ATT_V = 32768, ATT_AT = 49152;
constexpr int SATT = 65536;

__global__ void __launch_bounds__(256) k_attn3(const __half* __restrict__ q,
                                               const __half* __restrict__ k,
                                               const __half* __restrict__ v,
                                               __half* __restrict__ so0,
                                               __half* __restrict__ so1) {
    extern __shared__ __align__(16) char sm_raw[];
    const uint32_t sbase = smem_u32(sm_raw);
    const size_t base = (size_t)blockIdx.x * 8192;
    const int tid = threadIdx.x;
    const int wid = tid >> 5, lane = tid & 31;

    for (int u = tid; u < 4096; u += 256) {
        int n = u >> 6;
        int d = (u & 63) * 2;
        int h = d >> 6, dd = d & 63;
        uint32_t qp = *reinterpret_cast<const uint32_t*>(&q[base + 2 * u]);
        uint32_t kp = *reinterpret_cast<const uint32_t*>(&k[base + 2 * u]);
        uint32_t vp = *reinterpret_cast<const uint32_t*>(&v[base + 2 * u]);
        uint32_t off = sw128((n << 7) + (dd << 1));
        *reinterpret_cast<uint32_t*>(sm_raw + ATT_Q + h * 8192 + off) = qp;
        *reinterpret_cast<uint32_t*>(sm_raw + ATT_K + h * 8192 + off) = kp;
        *reinterpret_cast<uint16_t*>(sm_raw + ATT_V + h * 8192 +
            sw128((dd << 7) + (n << 1))) = (uint16_t)(vp & 0xffffu);
        *reinterpret_cast<uint16_t*>(sm_raw + ATT_V + h * 8192 +
            sw128(((dd + 1) << 7) + (n << 1))) = (uint16_t)(vp >> 16);
    }
    __syncthreads();

    const int sub = lane >> 3, lr = lane & 7;
    const int arow_off = (sub & 1) * 8 + lr;
    const int akc = (sub >> 1) * 8;
    const int brow_off = (sub >> 1) * 8 + lr;
    const int bkc = (sub & 1) * 8;
    const int qr = lane >> 2, qc = (lane & 3) * 2;

    float acc[8][4];

    {   // phase 1: attn = 0.125 * q.kT  (counts exact in fp16)
        const int h = wid & 1;
        const int n_b = (wid >> 1) * 16;
        uint32_t Abase = sbase + ATT_Q + h * 8192;
        uint32_t Bbase = sbase + ATT_K + h * 8192;
#pragma unroll
        for (int j = 0; j < 8; j++)
#pragma unroll
            for (int e = 0; e < 4; e++) acc[j][e] = 0.f;
#pragma unroll
        for (int ks = 0; ks < 4; ks++) {
            int k0 = ks * 16;
            uint32_t afr[4];
            ldsm4(afr, Abase + sw128(((n_b + arow_off) << 7) + (k0 + akc) * 2));
#pragma unroll
            for (int mf2 = 0; mf2 < 4; mf2++) {
                uint32_t bfr[4];
                ldsm4(bfr, Bbase + sw128(((mf2 * 16 + brow_off) << 7) + (k0 + bkc) * 2));
                mma16816(acc[mf2 * 2 + 0], afr, bfr[0], bfr[1]);
                mma16816(acc[mf2 * 2 + 1], afr, bfr[2], bfr[3]);
            }
        }
        uint32_t Obase = (uint32_t)(ATT_AT + h * 8192);
#pragma unroll
        for (int j = 0; j < 8; j++) {
            int m_col = j * 8 + qc;
            int r0 = n_b + qr;
            *reinterpret_cast<uint32_t*>(sm_raw + Obase +
                sw128((r0 << 7) + m_col * 2)) = h2x(acc[j][0] * 0.125f, acc[j][1] * 0.125f);
            *reinterpret_cast<uint32_t*>(sm_raw + Obase +
                sw128(((r0 + 8) << 7) + m_col * 2)) = h2x(acc[j][2] * 0.125f, acc[j][3] * 0.125f);
        }
    }
    __syncthreads();

    {   // phase 2: o = attn . vT, emit exact 2-way fp16 splits
        const int h = wid >> 2;
        const int n_b = (wid & 3) * 16;
        uint32_t Abase = sbase + ATT_AT + h * 8192;
        uint32_t Bbase = sbase + ATT_V + h * 8192;
#pragma unroll
        for (int j = 0; j < 8; j++)
#pragma unroll
            for (int e = 0; e < 4; e++) acc[j][e] = 0.f;
#pragma unroll
        for (int ks = 0; ks < 4; ks++) {
            int k0 = ks * 16;
            uint32_t afr[4];
            ldsm4(afr, Abase + sw128(((n_b + arow_off) << 7) + (k0 + akc) * 2));
#pragma unroll
            for (int df = 0; df < 4; df++) {
                uint32_t bfr[4];
                ldsm4(bfr, Bbase + sw128(((df * 16 + brow_off) << 7) + (k0 + bkc) * 2));
                mma16816(acc[df * 2 + 0], afr, bfr[0], bfr[1]);
                mma16816(acc[df * 2 + 1], afr, bfr[2], bfr[3]);
            }
        }
#pragma unroll
        for (int j = 0; j < 8; j++) {
            int d_col = h * 64 + j * 8 + qc;
#pragma unroll
            for (int half = 0; half < 2; half++) {
                int r0 = n_b + qr + half * 8;
                float f0 = acc[j][half * 2 + 0], f1 = acc[j][half * 2 + 1];
                float h0 = __half2float(__float2half_rn(f0));
                float h1v = __half2float(__float2half_rn(f1));
                size_t oi = base + (size_t)r0 * 128 + d_col;
                *reinterpret_cast<uint32_t*>(&so0[oi]) = h2x(f0, f1);
                *reinterpret_cast<uint32_t*>(&so1[oi]) =
                    h2x(__fsub_rn(f0, h0), __fsub_rn(f1, h1v));
            }
        }
    }
}

// =====================================================================
// Host side
// =====================================================================
extern "C" void kernel_launch(void* const* d_in, const int* in_sizes, int n_in,
                              void* d_out, int out_size) {
    const float* x  = (const float*)d_in[0];
    const float* mx = (const float*)d_in[1];
    const float* Wq = (const float*)d_in[2];
    const float* Wk = (const float*)d_in[3];
    const float* Wv = (const float*)d_in[4];
    const float* Wo = (const float*)d_in[5];
    const float* W1 = (const float*)d_in[6];
    const float* W2 = (const float*)d_in[7];
    float* out = (float*)d_out;

    void *p_xs, *p_ms, *p_os, *p_xgs, *p_xg, *p_q, *p_k, *p_v, *p_h1, *p_wsp;
    cudaGetSymbolAddress(&p_xs, g_xs);
    cudaGetSymbolAddress(&p_ms, g_ms);
    cudaGetSymbolAddress(&p_os, g_os);
    cudaGetSymbolAddress(&p_xgs, g_xgs);
    cudaGetSymbolAddress(&p_xg, g_xg);
    cudaGetSymbolAddress(&p_q, g_q);
    cudaGetSymbolAddress(&p_k, g_k);
    cudaGetSymbolAddress(&p_v, g_v);
    cudaGetSymbolAddress(&p_h1, g_h1);
    cudaGetSymbolAddress(&p_wsp, g_wsp);
    __half* xs = (__half*)p_xs;
    __half* ms = (__half*)p_ms;
    __half* os = (__half*)p_os;
    __half* xgs = (__half*)p_xgs;
    __half* wsp = (__half*)p_wsp;
    const size_t WSTRIDE = 2 * 128 * 256;

    cudaFuncSetAttribute(k_mmag<1, 0, 2, 1>, cudaFuncAttributeMaxDynamicSharedMemorySize, SGEMM);
    cudaFuncSetAttribute(k_mmag<1, 0, 2, 2>, cudaFuncAttributeMaxDynamicSharedMemorySize, SGEMM);
    cudaFuncSetAttribute(k_mmag<1, 1, 2, 1>, cudaFuncAttributeMaxDynamicSharedMemorySize, SGEMM);
    cudaFuncSetAttribute(k_mmag<2, 2, 1, 1>, cudaFuncAttributeMaxDynamicSharedMemorySize, SGEMM);
    cudaFuncSetAttribute(k_attn3, cudaFuncAttributeMaxDynamicSharedMemorySize, SATT);

    k_xsplit<<<2048, 256>>>(x);                                             // 1
    k_wsplit_all<<<512, 256>>>(Wq, Wk, Wv, Wo, W1, W2);                     // 2
    k_dct<<<64, 64>>>();                                                    // 3
    // q = LIF(x @ Wq)   <- launch #4: profiled
    k_mmag<1, 0, 2, 1><<<2048, 512, SGEMM>>>(xs, TOT, wsp + 0 * WSTRIDE, nullptr,
        p_q, nullptr, 128, 0, nullptr, nullptr, nullptr);                   // 4
    k_pack<<<32, 64>>>();                                                   // 5
    k_mix<<<4096, 256>>>(x, mx);                                            // 6
    // k,v = LIF(mlp @ Wk/Wv)  fused
    k_mmag<1, 0, 2, 2><<<4096, 512, SGEMM>>>(ms, TOT, wsp + 1 * WSTRIDE,
        wsp + 2 * WSTRIDE, p_k, p_v, 128, 0, nullptr, nullptr, nullptr);    // 7
    k_attn3<<<4096, 256, SATT>>>((const __half*)p_q, (const __half*)p_k,
        (const __half*)p_v, os, os + TOT);                                  // 8
    // xg = x * (1 - LIF(o @ Wo))
    k_mmag<1, 1, 2, 1><<<2048, 512, SGEMM>>>(os, TOT, wsp + 3 * WSTRIDE, nullptr,
        p_xg, nullptr, 128, 0, x, xgs, xgs + TOT);                          // 9
    // h1 = LIF(xg @ W1) (both N-halves fused)
    k_mmag<1, 0, 2, 2><<<4096, 512, SGEMM>>>(xgs, TOT, wsp + 4 * WSTRIDE,
        wsp + 5 * WSTRIDE, p_h1, p_h1, 256, 128, nullptr, nullptr, nullptr);// 10
    // out = xg * (1 - LIF(h1 @ W2))  (binary h1 -> 1 split, K=256)
    k_mmag<2, 2, 1, 1><<<2048, 512, SGEMM>>>((const __half*)p_h1, 0,
        wsp + 6 * WSTRIDE, nullptr, out, nullptr, 128, 0, (const float*)p_xg,
        nullptr, nullptr);                                                  // 11
}

// round 10
// speedup vs baseline: 1.6681x; 1.6681x over previous
#include <cuda_runtime.h>
#include <cuda_bf16.h>
#include <cuda_fp16.h>
#include <cstdint>

typedef unsigned long long ull;

constexpr int T_ = 64, B_ = 64, N_ = 64, D_ = 128, HID_ = 256;
constexpr int BND = B_ * N_ * D_;                      // 524288
constexpr size_t TOT  = (size_t)T_ * BND;              // 33554432
constexpr size_t TOTH = (size_t)T_ * B_ * N_ * HID_;   // 67108864

// -------- scratch (no allocations allowed) --------
__device__ float g_M[64 * 64];
__device__ ull   g_Mp[32 * 64];
__device__ __half g_xs[2][TOT];
__device__ __half g_ms[2][TOT];
__device__ __half g_os[2][TOT];
__device__ __half g_xgs[2][TOT];
__device__ float  g_xg[TOT];
__device__ __half g_q[TOT];
__device__ __half g_k[TOT];
__device__ __half g_v[TOT];
__device__ __half g_h1[TOTH];
__device__ __half g_wsp[7][2 * 128 * 256];

// -------- helpers --------
__device__ __forceinline__ void ffma2(ull& d, ull a, ull b) {
    asm("fma.rn.f32x2 %0, %1, %2, %0;" : "+l"(d) : "l"(a), "l"(b));
}
__device__ __forceinline__ ull dup2(float x) {
    ull r; unsigned u = __float_as_uint(x);
    asm("mov.b64 %0, {%1, %1};" : "=l"(r) : "r"(u));
    return r;
}
__device__ __forceinline__ ull pack2(float lo, float hi) {
    ull r;
    asm("mov.b64 %0, {%1, %2};" : "=l"(r) : "r"(__float_as_uint(lo)), "r"(__float_as_uint(hi)));
    return r;
}
__device__ __forceinline__ uint32_t smem_u32(const void* p) {
    uint32_t a;
    asm("{ .reg .u64 t; cvta.to.shared.u64 t, %1; cvt.u32.u64 %0, t; }" : "=r"(a) : "l"(p));
    return a;
}
__device__ __forceinline__ uint32_t sw128(uint32_t off) { return off ^ ((off >> 3) & 0x70); }
__device__ __forceinline__ void ldsm4(uint32_t* r, uint32_t addr) {
    asm volatile("ldmatrix.sync.aligned.m8n8.x4.shared.b16 {%0,%1,%2,%3}, [%4];"
                 : "=r"(r[0]), "=r"(r[1]), "=r"(r[2]), "=r"(r[3]) : "r"(addr));
}
__device__ __forceinline__ void mma16816(float* d, const uint32_t* a, uint32_t b0, uint32_t b1) {
    asm volatile(
        "mma.sync.aligned.m16n8k16.row.col.f32.f16.f16.f32 "
        "{%0,%1,%2,%3}, {%4,%5,%6,%7}, {%8,%9}, {%0,%1,%2,%3};"
        : "+f"(d[0]), "+f"(d[1]), "+f"(d[2]), "+f"(d[3])
        : "r"(a[0]), "r"(a[1]), "r"(a[2]), "r"(a[3]), "r"(b0), "r"(b1));
}
__device__ __forceinline__ uint32_t h2x(float lo, float hi) {
    uint32_t r;
    asm("cvt.rn.f16x2.f32 %0, %1, %2;" : "=r"(r) : "f"(hi), "f"(lo));
    return r;
}
__device__ __forceinline__ void cpa16(uint32_t dst, const void* src) {
    asm volatile("cp.async.cg.shared.global [%0], [%1], 16;" :: "r"(dst), "l"(src));
}
__device__ __forceinline__ void cpa_commit() { asm volatile("cp.async.commit_group;"); }
template <int NWAIT>
__device__ __forceinline__ void cpa_wait() {
    asm volatile("cp.async.wait_group %0;" :: "n"(NWAIT));
}

// =====================================================================
// DCT operator + packed form
// =====================================================================
__global__ void k_dct() {
    int t = blockIdx.x, s = threadIdx.x;
    const double PI = 3.141592653589793238462643383279502884;
    double acc = 0.0;
    for (int kk = 0; kk < 16; kk++) {
        double scale = (kk == 0) ? sqrt(1.0 / 64.0) : sqrt(2.0 / 64.0);
        float ct = (float)(cos(PI * (t + 0.5) * kk / 64.0) * scale);
        float cs = (float)(cos(PI * (s + 0.5) * kk / 64.0) * scale);
        acc += (double)ct * (double)cs;
    }
    g_M[t * 64 + s] = (float)acc;
}
__global__ void k_pack() {
    int t2 = blockIdx.x, s = threadIdx.x;
    g_Mp[t2 * 64 + s] = pack2(g_M[(2 * t2) * 64 + s], g_M[(2 * t2 + 1) * 64 + s]);
}

// =====================================================================
// Merged weight split (2-way fp16)
// =====================================================================
__global__ void k_wsplit_all(const float* __restrict__ Wq, const float* __restrict__ Wk,
                             const float* __restrict__ Wv, const float* __restrict__ Wo,
                             const float* __restrict__ W1, const float* __restrict__ W2) {
    int bi = blockIdx.x;
    int tile, ob;
    if (bi < 384) { tile = bi >> 6; ob = bi & 63; }
    else { tile = 6; ob = bi - 384; }
    const float* W; int ldw, col0, K;
    switch (tile) {
        case 0: W = Wq; ldw = 128; col0 = 0;   K = 128; break;
        case 1: W = Wk; ldw = 128; col0 = 0;   K = 128; break;
        case 2: W = Wv; ldw = 128; col0 = 0;   K = 128; break;
        case 3: W = Wo; ldw = 128; col0 = 0;   K = 128; break;
        case 4: W = W1; ldw = 256; col0 = 0;   K = 128; break;
        case 5: W = W1; ldw = 256; col0 = 128; K = 128; break;
        default: W = W2; ldw = 128; col0 = 0;  K = 256; break;
    }
    __half* out = &g_wsp[tile][0];
    int idx = ob * 256 + threadIdx.x;
    int n = idx / K, k = idx - n * K;
    float w = W[(size_t)k * ldw + col0 + n];
    __half hi = __float2half_rn(w);
    float r1 = __fsub_rn(w, __half2float(hi));
    out[(size_t)(0 * 128 + n) * K + k] = hi;
    out[(size_t)(1 * 128 + n) * K + k] = __float2half_rn(r1);
}

// =====================================================================
// x -> 2 fp16 splits, pure stream
// =====================================================================
__global__ void __launch_bounds__(256) k_xsplit(const float* __restrict__ x) {
    size_t i0 = ((size_t)blockIdx.x * 256 + threadIdx.x) * 8;
    const size_t step = (size_t)gridDim.x * 256 * 8;
    for (size_t i = i0; i < TOT; i += step) {
        float4 f0 = *reinterpret_cast<const float4*>(&x[i]);
        float4 f1 = *reinterpret_cast<const float4*>(&x[i + 4]);
        float a[8] = {f0.x, f0.y, f0.z, f0.w, f1.x, f1.y, f1.z, f1.w};
        uint32_t hp[4], lp[4];
#pragma unroll
        for (int e = 0; e < 4; e++) {
            float v0 = a[2 * e], v1 = a[2 * e + 1];
            __half h0 = __float2half_rn(v0), h1 = __float2half_rn(v1);
            float r0 = __fsub_rn(v0, __half2float(h0));
            float r1 = __fsub_rn(v1, __half2float(h1));
            hp[e] = (uint32_t)*(uint16_t*)&h0 | ((uint32_t)*(uint16_t*)&h1 << 16);
            lp[e] = h2x(r0, r1);
        }
        *reinterpret_cast<uint4*>(&g_xs[0][i]) = *reinterpret_cast<uint4*>(hp);
        *reinterpret_cast<uint4*>(&g_xs[1][i]) = *reinterpret_cast<uint4*>(lp);
    }
}

// =====================================================================
// Memory mix + temporal lowpass; emits 2 fp16 splits
// =====================================================================
__global__ void __launch_bounds__(256) k_mix(const float* __restrict__ x,
                                             const float* __restrict__ mx) {
    __shared__ float s_p[64 * 128];
    __shared__ ull  s_Mp[32 * 64];
    const int bn = blockIdx.x;
    const int b = bn >> 6, n = bn & 63;
    const int tid = threadIdx.x;

    for (int i = tid; i < 2048; i += 256) s_Mp[i] = g_Mp[i];

    const float* xb = x + (size_t)(b * N_ + n) * D_;
    const float* mb = mx + ((size_t)(n * B_ + b) * T_) * D_;
    for (int i = tid; i < 8192; i += 256) {
        float mv = mb[i];
        float mv2 = __fadd_rn(__fmul_rn(0.05f, mv), __fmul_rn(0.95f, mv));
        s_p[i] = __fmul_rn(xb[(size_t)(i >> 7) * BND + (i & 127)], mv2);
    }
    __syncthreads();

    const int d = tid & 127;
    const int t2b = (tid >> 7) * 16;
    ull acc[16];
#pragma unroll
    for (int j = 0; j < 16; j++) acc[j] = 0ull;
    for (int s = 0; s < 64; s++) {
        ull cp = dup2(s_p[s * 128 + d]);
#pragma unroll
        for (int j = 0; j < 16; j++) ffma2(acc[j], s_Mp[(t2b + j) * 64 + s], cp);
    }
#pragma unroll
    for (int j = 0; j < 16; j++) {
        float2 f = *reinterpret_cast<float2*>(&acc[j]);
#pragma unroll
        for (int e = 0; e < 2; e++) {
            float v = (e == 0) ? f.x : f.y;
            size_t oi = ((size_t)(2 * (t2b + j) + e) * 4096 + bn) * 128 + d;
            __half hi = __float2half_rn(v);
            float r1 = __fsub_rn(v, __half2float(hi));
            g_ms[0][oi] = hi;
            g_ms[1][oi] = __float2half_rn(r1);
        }
    }
}

// =====================================================================
// fp16 tensor-core GEMM + fused LIF. 256 threads, 8 warps, warp tile
// 64x32, single 64KB stage buffer, 2 CTAs/SM (cross-CTA overlap).
// =====================================================================
constexpr int SGEMM = 1024 + 128 * 130 * 4;   // 67584 (stage 64KB overlaid by s_pre)
constexpr int PPAD = 130;

template <int KCHUNKS, int MODE, int NSPLITS, int NSEL>
__global__ void __launch_bounds__(256, 2) k_mmag(
    const __half* __restrict__ aspl, size_t asstride,
    const __half* __restrict__ wspA, const __half* __restrict__ wspB,
    void* __restrict__ outA, void* __restrict__ outB,
    int ldo, int ocolmul,
    const float* __restrict__ gx,
    __half* __restrict__ so0, __half* __restrict__ so1) {
    extern __shared__ __align__(16) char smem_raw[];
    const uint32_t sbase = smem_u32(smem_raw);
    float* s_pre = (float*)(smem_raw + 1024);
    const int sel = (NSEL == 2) ? (int)(blockIdx.x >> 11) : 0;
    const int bn0 = ((NSEL == 2) ? (blockIdx.x & 2047) : blockIdx.x) * 2;
    const __half* wsp = sel ? wspB : wspA;
    void* outp = sel ? outB : outA;
    const int ocol0 = ocolmul * sel;
    const int tid = threadIdx.x;
    const int wid = tid >> 5, lane = tid & 31;
    constexpr int KTOT = KCHUNKS * 128;
    constexpr int NST = KCHUNKS * 2;

    const int m_base = (wid & 1) * 64;
    const int n_base = (wid >> 1) * 32;
    const int sub = lane >> 3, lr = lane & 7;
    const int arow_off = (sub & 1) * 8 + lr;
    const int akc = (sub >> 1) * 8;
    const int brow_off = (sub >> 1) * 8 + lr;
    const int bkc = (sub & 1) * 8;

    auto load_stage = [&](int s) {
        const int ch = s >> 1, kh = s & 1;
        const uint32_t dst = sbase + 1024;
        for (int u = tid; u < NSPLITS * 1024; u += 256) {
            int sp = u >> 10, r = u & 1023, m = r >> 3, g = r & 7;
            int t = m & 63, tile = m >> 6;
            const __half* src = aspl + (size_t)sp * asstride +
                ((size_t)t * 4096 + bn0 + tile) * KTOT + ch * 128 + kh * 64 + g * 8;
            cpa16(dst + sp * 16384 + sw128((m << 7) + (g << 4)), src);
        }
        for (int u = tid; u < 2048; u += 256) {
            int sp = u >> 10, r = u & 1023, n = r >> 3, g = r & 7;
            const __half* src =
                wsp + ((size_t)(sp * 128 + n) * KTOT + ch * 128 + kh * 64 + g * 8);
            cpa16(dst + 32768 + sp * 16384 + sw128((n << 7) + (g << 4)), src);
        }
        cpa_commit();
    };

    float acc[4][4][4];
#pragma unroll
    for (int i = 0; i < 4; i++)
#pragma unroll
        for (int j = 0; j < 4; j++)
#pragma unroll
            for (int e = 0; e < 4; e++) acc[i][j][e] = 0.f;

#pragma unroll
    for (int s = 0; s < NST; s++) {
        if (s) __syncthreads();       // previous stage fully consumed
        load_stage(s);
        cpa_wait<0>();
        __syncthreads();

        const uint32_t Abuf = sbase + 1024;
        const uint32_t Bbuf = Abuf + 32768;
        const int NP = (NSPLITS == 2) ? 3 : 2;
        const int PAs[3] = {0, 0, 1};
        const int PBs[3] = {0, 1, 0};
        const int PB1[3] = {0, 1, 0};

        for (int p = 0; p < NP; p++) {
            int As = (NSPLITS == 1) ? 0 : PAs[p];
            int Bs = (NSPLITS == 1) ? PB1[p] : PBs[p];
            uint32_t Abase = Abuf + As * 16384;
            uint32_t Bbase = Bbuf + Bs * 16384;
#pragma unroll
            for (int ks = 0; ks < 4; ks++) {
                int k0 = ks * 16;
                uint32_t afr[4][4];
#pragma unroll
                for (int mf = 0; mf < 4; mf++)
                    ldsm4(afr[mf], Abase +
                          sw128(((m_base + mf * 16 + arow_off) << 7) + (k0 + akc) * 2));
                uint32_t bfr[2][4];
#pragma unroll
                for (int nf2 = 0; nf2 < 2; nf2++)
                    ldsm4(bfr[nf2], Bbase +
                          sw128(((n_base + nf2 * 16 + brow_off) << 7) + (k0 + bkc) * 2));
#pragma unroll
                for (int mf = 0; mf < 4; mf++)
#pragma unroll
                    for (int nf = 0; nf < 4; nf++)
                        mma16816(acc[mf][nf], afr[mf],
                                 bfr[nf >> 1][(nf & 1) * 2], bfr[nf >> 1][(nf & 1) * 2 + 1]);
            }
        }
    }
    __syncthreads();

    // ---- store fragments to s_pre ----
    {
        const int qr = lane >> 2, qc = (lane & 3) * 2;
#pragma unroll
        for (int mf = 0; mf < 4; mf++)
#pragma unroll
            for (int nf = 0; nf < 4; nf++) {
                int row = m_base + mf * 16 + qr;
                int col = n_base + nf * 8 + qc;
                *reinterpret_cast<float2*>(&s_pre[row * PPAD + col]) =
                    make_float2(acc[mf][nf][0], acc[mf][nf][1]);
                *reinterpret_cast<float2*>(&s_pre[(row + 8) * PPAD + col]) =
                    make_float2(acc[mf][nf][2], acc[mf][nf][3]);
            }
    }
    __syncthreads();

    // ---- fused LIF scan ----
    {
        const int tile = tid >> 7, c = tid & 127;
        const int bn = bn0 + tile;
        float vmem = 0.f;
        const size_t ostride = (size_t)4096 * ldo;
        const size_t obase = (size_t)bn * ldo + ocol0 + c;
        const size_t gbase = (size_t)bn * 128 + c;
#pragma unroll 1
        for (int t = 0; t < 64; t++) {
            float p = s_pre[(tile * 64 + t) * PPAD + c];
            vmem = __fadd_rn(vmem, __fmul_rn(__fsub_rn(p, vmem), 0.5f));
            float spk = (vmem >= 1.0f) ? 1.0f : 0.0f;
            if (vmem >= 1.0f) vmem = 0.0f;
            size_t oi = obase + (size_t)t * ostride;
            if (MODE == 0) {
                ((__half*)outp)[oi] = __float2half_rn(spk);
            } else {
                float g = gx[gbase + (size_t)t * (size_t)BND];
                float val = __fmul_rn(g, __fsub_rn(1.0f, spk));
                ((float*)outp)[oi] = val;
                if (MODE == 1) {
                    __half hi = __float2half_rn(val);
                    float r1 = __fsub_rn(val, __half2float(hi));
                    so0[oi] = hi;
                    so1[oi] = __float2half_rn(r1);
                }
            }
        }
    }
}

// =====================================================================
// Attention via tensor cores (exact fp16 in/out), emits o splits.
// =====================================================================
constexpr int ATT_Q = 0, ATT_K = 16384, ATT_V = 32768, ATT_AT = 49152;
constexpr int SATT = 65536;

__global__ void __launch_bounds__(256) k_attn3(const __half* __restrict__ q,
                                               const __half* __restrict__ k,
                                               const __half* __restrict__ v,
                                               __half* __restrict__ so0,
                                               __half* __restrict__ so1) {
    extern __shared__ __align__(16) char sm_raw[];
    const uint32_t sbase = smem_u32(sm_raw);
    const size_t base = (size_t)blockIdx.x * 8192;
    const int tid = threadIdx.x;
    const int wid = tid >> 5, lane = tid & 31;

    for (int u = tid; u < 4096; u += 256) {
        int n = u >> 6;
        int d = (u & 63) * 2;
        int h = d >> 6, dd = d & 63;
        uint32_t qp = *reinterpret_cast<const uint32_t*>(&q[base + 2 * u]);
        uint32_t kp = *reinterpret_cast<const uint32_t*>(&k[base + 2 * u]);
        uint32_t vp = *reinterpret_cast<const uint32_t*>(&v[base + 2 * u]);
        uint32_t off = sw128((n << 7) + (dd << 1));
        *reinterpret_cast<uint32_t*>(sm_raw + ATT_Q + h * 8192 + off) = qp;
        *reinterpret_cast<uint32_t*>(sm_raw + ATT_K + h * 8192 + off) = kp;
        *reinterpret_cast<uint16_t*>(sm_raw + ATT_V + h * 8192 +
            sw128((dd << 7) + (n << 1))) = (uint16_t)(vp & 0xffffu);
        *reinterpret_cast<uint16_t*>(sm_raw + ATT_V + h * 8192 +
            sw128(((dd + 1) << 7) + (n << 1))) = (uint16_t)(vp >> 16);
    }
    __syncthreads();

    const int sub = lane >> 3, lr = lane & 7;
    const int arow_off = (sub & 1) * 8 + lr;
    const int akc = (sub >> 1) * 8;
    const int brow_off = (sub >> 1) * 8 + lr;
    const int bkc = (sub & 1) * 8;
    const int qr = lane >> 2, qc = (lane & 3) * 2;

    float acc[8][4];

    {   // phase 1: attn = 0.125 * q.kT
        const int h = wid & 1;
        const int n_b = (wid >> 1) * 16;
        uint32_t Abase = sbase + ATT_Q + h * 8192;
        uint32_t Bbase = sbase + ATT_K + h * 8192;
#pragma unroll
        for (int j = 0; j < 8; j++)
#pragma unroll
            for (int e = 0; e < 4; e++) acc[j][e] = 0.f;
#pragma unroll
        for (int ks = 0; ks < 4; ks++) {
            int k0 = ks * 16;
            uint32_t afr[4];
            ldsm4(afr, Abase + sw128(((n_b + arow_off) << 7) + (k0 + akc) * 2));
#pragma unroll
            for (int mf2 = 0; mf2 < 4; mf2++) {
                uint32_t bfr[4];
                ldsm4(bfr, Bbase + sw128(((mf2 * 16 + brow_off) << 7) + (k0 + bkc) * 2));
                mma16816(acc[mf2 * 2 + 0], afr, bfr[0], bfr[1]);
                mma16816(acc[mf2 * 2 + 1], afr, bfr[2], bfr[3]);
            }
        }
        uint32_t Obase = (uint32_t)(ATT_AT + h * 8192);
#pragma unroll
        for (int j = 0; j < 8; j++) {
            int m_col = j * 8 + qc;
            int r0 = n_b + qr;
            *reinterpret_cast<uint32_t*>(sm_raw + Obase +
                sw128((r0 << 7) + m_col * 2)) = h2x(acc[j][0] * 0.125f, acc[j][1] * 0.125f);
            *reinterpret_cast<uint32_t*>(sm_raw + Obase +
                sw128(((r0 + 8) << 7) + m_col * 2)) = h2x(acc[j][2] * 0.125f, acc[j][3] * 0.125f);
        }
    }
    __syncthreads();

    {   // phase 2: o = attn . vT, emit exact 2-way fp16 splits
        const int h = wid >> 2;
        const int n_b = (wid & 3) * 16;
        uint32_t Abase = sbase + ATT_AT + h * 8192;
        uint32_t Bbase = sbase + ATT_V + h * 8192;
#pragma unroll
        for (int j = 0; j < 8; j++)
#pragma unroll
            for (int e = 0; e < 4; e++) acc[j][e] = 0.f;
#pragma unroll
        for (int ks = 0; ks < 4; ks++) {
            int k0 = ks * 16;
            uint32_t afr[4];
            ldsm4(afr, Abase + sw128(((n_b + arow_off) << 7) + (k0 + akc) * 2));
#pragma unroll
            for (int df = 0; df < 4; df++) {
                uint32_t bfr[4];
                ldsm4(bfr, Bbase + sw128(((df * 16 + brow_off) << 7) + (k0 + bkc) * 2));
                mma16816(acc[df * 2 + 0], afr, bfr[0], bfr[1]);
                mma16816(acc[df * 2 + 1], afr, bfr[2], bfr[3]);
            }
        }
#pragma unroll
        for (int j = 0; j < 8; j++) {
            int d_col = h * 64 + j * 8 + qc;
#pragma unroll
            for (int half = 0; half < 2; half++) {
                int r0 = n_b + qr + half * 8;
                float f0 = acc[j][half * 2 + 0], f1 = acc[j][half * 2 + 1];
                float h0 = __half2float(__float2half_rn(f0));
                float h1v = __half2float(__float2half_rn(f1));
                size_t oi = base + (size_t)r0 * 128 + d_col;
                *reinterpret_cast<uint32_t*>(&so0[oi]) = h2x(f0, f1);
                *reinterpret_cast<uint32_t*>(&so1[oi]) =
                    h2x(__fsub_rn(f0, h0), __fsub_rn(f1, h1v));
            }
        }
    }
}

// =====================================================================
// Host side
// =====================================================================
extern "C" void kernel_launch(void* const* d_in, const int* in_sizes, int n_in,
                              void* d_out, int out_size) {
    const float* x  = (const float*)d_in[0];
    const float* mx = (const float*)d_in[1];
    const float* Wq = (const float*)d_in[2];
    const float* Wk = (const float*)d_in[3];
    const float* Wv = (const float*)d_in[4];
    const float* Wo = (const float*)d_in[5];
    const float* W1 = (const float*)d_in[6];
    const float* W2 = (const float*)d_in[7];
    float* out = (float*)d_out;

    void *p_xs, *p_ms, *p_os, *p_xgs, *p_xg, *p_q, *p_k, *p_v, *p_h1, *p_wsp;
    cudaGetSymbolAddress(&p_xs, g_xs);
    cudaGetSymbolAddress(&p_ms, g_ms);
    cudaGetSymbolAddress(&p_os, g_os);
    cudaGetSymbolAddress(&p_xgs, g_xgs);
    cudaGetSymbolAddress(&p_xg, g_xg);
    cudaGetSymbolAddress(&p_q, g_q);
    cudaGetSymbolAddress(&p_k, g_k);
    cudaGetSymbolAddress(&p_v, g_v);
    cudaGetSymbolAddress(&p_h1, g_h1);
    cudaGetSymbolAddress(&p_wsp, g_wsp);
    __half* xs = (__half*)p_xs;
    __half* ms = (__half*)p_ms;
    __half* os = (__half*)p_os;
    __half* xgs = (__half*)p_xgs;
    __half* wsp = (__half*)p_wsp;
    const size_t WSTRIDE = 2 * 128 * 256;

    cudaFuncSetAttribute(k_mmag<1, 0, 2, 1>, cudaFuncAttributeMaxDynamicSharedMemorySize, SGEMM);
    cudaFuncSetAttribute(k_mmag<1, 0, 2, 2>, cudaFuncAttributeMaxDynamicSharedMemorySize, SGEMM);
    cudaFuncSetAttribute(k_mmag<1, 1, 2, 1>, cudaFuncAttributeMaxDynamicSharedMemorySize, SGEMM);
    cudaFuncSetAttribute(k_mmag<2, 2, 1, 1>, cudaFuncAttributeMaxDynamicSharedMemorySize, SGEMM);
    cudaFuncSetAttribute(k_attn3, cudaFuncAttributeMaxDynamicSharedMemorySize, SATT);

    k_xsplit<<<2048, 256>>>(x);                                             // 1
    k_wsplit_all<<<512, 256>>>(Wq, Wk, Wv, Wo, W1, W2);                     // 2
    k_dct<<<64, 64>>>();                                                    // 3
    // q = LIF(x @ Wq)   <- launch #4: profiled
    k_mmag<1, 0, 2, 1><<<2048, 256, SGEMM>>>(xs, TOT, wsp + 0 * WSTRIDE, nullptr,
        p_q, nullptr, 128, 0, nullptr, nullptr, nullptr);                   // 4
    k_pack<<<32, 64>>>();                                                   // 5
    k_mix<<<4096, 256>>>(x, mx);                                            // 6
    // k,v = LIF(mlp @ Wk/Wv)  fused
    k_mmag<1, 0, 2, 2><<<4096, 256, SGEMM>>>(ms, TOT, wsp + 1 * WSTRIDE,
        wsp + 2 * WSTRIDE, p_k, p_v, 128, 0, nullptr, nullptr, nullptr);    // 7
    k_attn3<<<4096, 256, SATT>>>((const __half*)p_q, (const __half*)p_k,
        (const __half*)p_v, os, os + TOT);                                  // 8
    // xg = x * (1 - LIF(o @ Wo))
    k_mmag<1, 1, 2, 1><<<2048, 256, SGEMM>>>(os, TOT, wsp + 3 * WSTRIDE, nullptr,
        p_xg, nullptr, 128, 0, x, xgs, xgs + TOT);                          // 9
    // h1 = LIF(xg @ W1) (both N-halves fused)
    k_mmag<1, 0, 2, 2><<<4096, 256, SGEMM>>>(xgs, TOT, wsp + 4 * WSTRIDE,
        wsp + 5 * WSTRIDE, p_h1, p_h1, 256, 128, nullptr, nullptr, nullptr);// 10
    // out = xg * (1 - LIF(h1 @ W2))  (binary h1 -> 1 split, K=256)
    k_mmag<2, 2, 1, 1><<<2048, 256, SGEMM>>>((const __half*)p_h1, 0,
        wsp + 6 * WSTRIDE, nullptr, out, nullptr, 128, 0, (const float*)p_xg,
        nullptr, nullptr);                                                  // 11
}

// round 11
// speedup vs baseline: 1.6785x; 1.0062x over previous
#include <cuda_runtime.h>
#include <cuda_bf16.h>
#include <cuda_fp16.h>
#include <cstdint>

typedef unsigned long long ull;

constexpr int T_ = 64, B_ = 64, N_ = 64, D_ = 128, HID_ = 256;
constexpr int BND = B_ * N_ * D_;                      // 524288
constexpr size_t TOT  = (size_t)T_ * BND;              // 33554432
constexpr size_t TOTH = (size_t)T_ * B_ * N_ * HID_;   // 67108864

// -------- scratch (no allocations allowed) --------
__device__ float g_M[64 * 64];
__device__ ull   g_Mp[32 * 64];
__device__ __half g_xs[2][TOT];
__device__ __half g_ms[2][TOT];
__device__ __half g_os[2][TOT];
__device__ __half g_xgs[2][TOT];
__device__ float  g_xg[TOT];
__device__ __half g_q[TOT];
__device__ __half g_k[TOT];
__device__ __half g_v[TOT];
__device__ __half g_h1[TOTH];
__device__ __half g_wsp[7][2 * 128 * 256];

// -------- helpers --------
__device__ __forceinline__ void ffma2(ull& d, ull a, ull b) {
    asm("fma.rn.f32x2 %0, %1, %2, %0;" : "+l"(d) : "l"(a), "l"(b));
}
__device__ __forceinline__ ull dup2(float x) {
    ull r; unsigned u = __float_as_uint(x);
    asm("mov.b64 %0, {%1, %1};" : "=l"(r) : "r"(u));
    return r;
}
__device__ __forceinline__ ull pack2(float lo, float hi) {
    ull r;
    asm("mov.b64 %0, {%1, %2};" : "=l"(r) : "r"(__float_as_uint(lo)), "r"(__float_as_uint(hi)));
    return r;
}
__device__ __forceinline__ uint32_t smem_u32(const void* p) {
    uint32_t a;
    asm("{ .reg .u64 t; cvta.to.shared.u64 t, %1; cvt.u32.u64 %0, t; }" : "=r"(a) : "l"(p));
    return a;
}
__device__ __forceinline__ uint32_t sw128(uint32_t off) { return off ^ ((off >> 3) & 0x70); }
__device__ __forceinline__ void ldsm4(uint32_t* r, uint32_t addr) {
    asm volatile("ldmatrix.sync.aligned.m8n8.x4.shared.b16 {%0,%1,%2,%3}, [%4];"
                 : "=r"(r[0]), "=r"(r[1]), "=r"(r[2]), "=r"(r[3]) : "r"(addr));
}
__device__ __forceinline__ void mma16816(float* d, const uint32_t* a, uint32_t b0, uint32_t b1) {
    asm volatile(
        "mma.sync.aligned.m16n8k16.row.col.f32.f16.f16.f32 "
        "{%0,%1,%2,%3}, {%4,%5,%6,%7}, {%8,%9}, {%0,%1,%2,%3};"
        : "+f"(d[0]), "+f"(d[1]), "+f"(d[2]), "+f"(d[3])
        : "r"(a[0]), "r"(a[1]), "r"(a[2]), "r"(a[3]), "r"(b0), "r"(b1));
}
__device__ __forceinline__ uint32_t h2x(float lo, float hi) {
    uint32_t r;
    asm("cvt.rn.f16x2.f32 %0, %1, %2;" : "=r"(r) : "f"(hi), "f"(lo));
    return r;
}
__device__ __forceinline__ void cpa16(uint32_t dst, const void* src) {
    asm volatile("cp.async.cg.shared.global [%0], [%1], 16;" :: "r"(dst), "l"(src));
}
__device__ __forceinline__ void cpa_commit() { asm volatile("cp.async.commit_group;"); }
template <int NWAIT>
__device__ __forceinline__ void cpa_wait() {
    asm volatile("cp.async.wait_group %0;" :: "n"(NWAIT));
}

// =====================================================================
// DCT operator + packed form
// =====================================================================
__global__ void k_dct() {
    int t = blockIdx.x, s = threadIdx.x;
    const double PI = 3.141592653589793238462643383279502884;
    double acc = 0.0;
    for (int kk = 0; kk < 16; kk++) {
        double scale = (kk == 0) ? sqrt(1.0 / 64.0) : sqrt(2.0 / 64.0);
        float ct = (float)(cos(PI * (t + 0.5) * kk / 64.0) * scale);
        float cs = (float)(cos(PI * (s + 0.5) * kk / 64.0) * scale);
        acc += (double)ct * (double)cs;
    }
    g_M[t * 64 + s] = (float)acc;
}
__global__ void k_pack() {
    int t2 = blockIdx.x, s = threadIdx.x;
    g_Mp[t2 * 64 + s] = pack2(g_M[(2 * t2) * 64 + s], g_M[(2 * t2 + 1) * 64 + s]);
}

// =====================================================================
// Merged weight split (2-way fp16)
// =====================================================================
__global__ void k_wsplit_all(const float* __restrict__ Wq, const float* __restrict__ Wk,
                             const float* __restrict__ Wv, const float* __restrict__ Wo,
                             const float* __restrict__ W1, const float* __restrict__ W2) {
    int bi = blockIdx.x;
    int tile, ob;
    if (bi < 384) { tile = bi >> 6; ob = bi & 63; }
    else { tile = 6; ob = bi - 384; }
    const float* W; int ldw, col0, K;
    switch (tile) {
        case 0: W = Wq; ldw = 128; col0 = 0;   K = 128; break;
        case 1: W = Wk; ldw = 128; col0 = 0;   K = 128; break;
        case 2: W = Wv; ldw = 128; col0 = 0;   K = 128; break;
        case 3: W = Wo; ldw = 128; col0 = 0;   K = 128; break;
        case 4: W = W1; ldw = 256; col0 = 0;   K = 128; break;
        case 5: W = W1; ldw = 256; col0 = 128; K = 128; break;
        default: W = W2; ldw = 128; col0 = 0;  K = 256; break;
    }
    __half* out = &g_wsp[tile][0];
    int idx = ob * 256 + threadIdx.x;
    int n = idx / K, k = idx - n * K;
    float w = W[(size_t)k * ldw + col0 + n];
    __half hi = __float2half_rn(w);
    float r1 = __fsub_rn(w, __half2float(hi));
    out[(size_t)(0 * 128 + n) * K + k] = hi;
    out[(size_t)(1 * 128 + n) * K + k] = __float2half_rn(r1);
}

// =====================================================================
// x -> 2 fp16 splits, pure stream
// =====================================================================
__global__ void __launch_bounds__(256) k_xsplit(const float* __restrict__ x) {
    size_t i0 = ((size_t)blockIdx.x * 256 + threadIdx.x) * 8;
    const size_t step = (size_t)gridDim.x * 256 * 8;
    for (size_t i = i0; i < TOT; i += step) {
        float4 f0 = *reinterpret_cast<const float4*>(&x[i]);
        float4 f1 = *reinterpret_cast<const float4*>(&x[i + 4]);
        float a[8] = {f0.x, f0.y, f0.z, f0.w, f1.x, f1.y, f1.z, f1.w};
        uint32_t hp[4], lp[4];
#pragma unroll
        for (int e = 0; e < 4; e++) {
            float v0 = a[2 * e], v1 = a[2 * e + 1];
            __half h0 = __float2half_rn(v0), h1 = __float2half_rn(v1);
            float r0 = __fsub_rn(v0, __half2float(h0));
            float r1 = __fsub_rn(v1, __half2float(h1));
            hp[e] = (uint32_t)*(uint16_t*)&h0 | ((uint32_t)*(uint16_t*)&h1 << 16);
            lp[e] = h2x(r0, r1);
        }
        *reinterpret_cast<uint4*>(&g_xs[0][i]) = *reinterpret_cast<uint4*>(hp);
        *reinterpret_cast<uint4*>(&g_xs[1][i]) = *reinterpret_cast<uint4*>(lp);
    }
}

// =====================================================================
// Memory mix + temporal lowpass; emits 2 fp16 splits
// =====================================================================
__global__ void __launch_bounds__(256) k_mix(const float* __restrict__ x,
                                             const float* __restrict__ mx) {
    __shared__ float s_p[64 * 128];
    __shared__ ull  s_Mp[32 * 64];
    const int bn = blockIdx.x;
    const int b = bn >> 6, n = bn & 63;
    const int tid = threadIdx.x;

    for (int i = tid; i < 2048; i += 256) s_Mp[i] = g_Mp[i];

    const float* xb = x + (size_t)(b * N_ + n) * D_;
    const float* mb = mx + ((size_t)(n * B_ + b) * T_) * D_;
    for (int i = tid; i < 8192; i += 256) {
        float mv = mb[i];
        float mv2 = __fadd_rn(__fmul_rn(0.05f, mv), __fmul_rn(0.95f, mv));
        s_p[i] = __fmul_rn(xb[(size_t)(i >> 7) * BND + (i & 127)], mv2);
    }
    __syncthreads();

    const int d = tid & 127;
    const int t2b = (tid >> 7) * 16;
    ull acc[16];
#pragma unroll
    for (int j = 0; j < 16; j++) acc[j] = 0ull;
    for (int s = 0; s < 64; s++) {
        ull cp = dup2(s_p[s * 128 + d]);
#pragma unroll
        for (int j = 0; j < 16; j++) ffma2(acc[j], s_Mp[(t2b + j) * 64 + s], cp);
    }
#pragma unroll
    for (int j = 0; j < 16; j++) {
        float2 f = *reinterpret_cast<float2*>(&acc[j]);
#pragma unroll
        for (int e = 0; e < 2; e++) {
            float v = (e == 0) ? f.x : f.y;
            size_t oi = ((size_t)(2 * (t2b + j) + e) * 4096 + bn) * 128 + d;
            __half hi = __float2half_rn(v);
            float r1 = __fsub_rn(v, __half2float(hi));
            g_ms[0][oi] = hi;
            g_ms[1][oi] = __float2half_rn(r1);
        }
    }
}

// =====================================================================
// fp16 tensor-core GEMM + fused LIF. 128 threads, 4 warps, M=64 per CTA,
// warp tile 64x32, single 48KB stage, 4 CTAs/SM (cross-CTA overlap).
// =====================================================================
constexpr int SGEMM = 1024 + 48 * 1024;       // 50176; s_pre (64*130*4) overlays
constexpr int PPAD = 130;

template <int KCHUNKS, int MODE, int NSPLITS, int NSEL>
__global__ void __launch_bounds__(128, 4) k_mmag(
    const __half* __restrict__ aspl, size_t asstride,
    const __half* __restrict__ wspA, const __half* __restrict__ wspB,
    void* __restrict__ outA, void* __restrict__ outB,
    int ldo, int ocolmul,
    const float* __restrict__ gx,
    __half* __restrict__ so0, __half* __restrict__ so1) {
    extern __shared__ __align__(16) char smem_raw[];
    const uint32_t sbase = smem_u32(smem_raw);
    float* s_pre = (float*)(smem_raw + 1024);
    const int sel = (NSEL == 2) ? (int)(blockIdx.x >> 12) : 0;
    const int bn = (NSEL == 2) ? (blockIdx.x & 4095) : blockIdx.x;
    const __half* wsp = sel ? wspB : wspA;
    void* outp = sel ? outB : outA;
    const int ocol0 = ocolmul * sel;
    const int tid = threadIdx.x;
    const int wid = tid >> 5, lane = tid & 31;
    constexpr int KTOT = KCHUNKS * 128;
    constexpr int NST = KCHUNKS * 2;

    const int n_base = wid * 32;
    const int sub = lane >> 3, lr = lane & 7;
    const int arow_off = (sub & 1) * 8 + lr;
    const int akc = (sub >> 1) * 8;
    const int brow_off = (sub >> 1) * 8 + lr;
    const int bkc = (sub & 1) * 8;

    // A tiles: 2 x 8KB (64m x 64k), B tiles: 2 x 16KB (128n x 64k)
    auto load_stage = [&](int s) {
        const int ch = s >> 1, kh = s & 1;
        const uint32_t dst = sbase + 1024;
        for (int u = tid; u < NSPLITS * 512; u += 128) {
            int sp = u >> 9, r = u & 511, m = r >> 3, g = r & 7;
            const __half* src = aspl + (size_t)sp * asstride +
                ((size_t)m * 4096 + bn) * KTOT + ch * 128 + kh * 64 + g * 8;
            cpa16(dst + sp * 8192 + sw128((m << 7) + (g << 4)), src);
        }
        for (int u = tid; u < 2048; u += 128) {
            int sp = u >> 10, r = u & 1023, n = r >> 3, g = r & 7;
            const __half* src =
                wsp + ((size_t)(sp * 128 + n) * KTOT + ch * 128 + kh * 64 + g * 8);
            cpa16(dst + 16384 + sp * 16384 + sw128((n << 7) + (g << 4)), src);
        }
        cpa_commit();
    };

    float acc[4][4][4];
#pragma unroll
    for (int i = 0; i < 4; i++)
#pragma unroll
        for (int j = 0; j < 4; j++)
#pragma unroll
            for (int e = 0; e < 4; e++) acc[i][j][e] = 0.f;

#pragma unroll
    for (int s = 0; s < NST; s++) {
        if (s) __syncthreads();
        load_stage(s);
        cpa_wait<0>();
        __syncthreads();

        const uint32_t Abuf = sbase + 1024;
        const uint32_t Bbuf = Abuf + 16384;
        const int NP = (NSPLITS == 2) ? 3 : 2;
        const int PAs[3] = {0, 0, 1};
        const int PBs[3] = {0, 1, 0};
        const int PB1[3] = {0, 1, 0};

        for (int p = 0; p < NP; p++) {
            int As = (NSPLITS == 1) ? 0 : PAs[p];
            int Bs = (NSPLITS == 1) ? PB1[p] : PBs[p];
            uint32_t Abase = Abuf + As * 8192;
            uint32_t Bbase = Bbuf + Bs * 16384;
#pragma unroll
            for (int ks = 0; ks < 4; ks++) {
                int k0 = ks * 16;
                uint32_t afr[4][4];
#pragma unroll
                for (int mf = 0; mf < 4; mf++)
                    ldsm4(afr[mf], Abase +
                          sw128(((mf * 16 + arow_off) << 7) + (k0 + akc) * 2));
                uint32_t bfr[2][4];
#pragma unroll
                for (int nf2 = 0; nf2 < 2; nf2++)
                    ldsm4(bfr[nf2], Bbase +
                          sw128(((n_base + nf2 * 16 + brow_off) << 7) + (k0 + bkc) * 2));
#pragma unroll
                for (int mf = 0; mf < 4; mf++)
#pragma unroll
                    for (int nf = 0; nf < 4; nf++)
                        mma16816(acc[mf][nf], afr[mf],
                                 bfr[nf >> 1][(nf & 1) * 2], bfr[nf >> 1][(nf & 1) * 2 + 1]);
            }
        }
    }
    __syncthreads();

    // ---- store fragments to s_pre (64 x 128) ----
    {
        const int qr = lane >> 2, qc = (lane & 3) * 2;
#pragma unroll
        for (int mf = 0; mf < 4; mf++)
#pragma unroll
            for (int nf = 0; nf < 4; nf++) {
                int row = mf * 16 + qr;
                int col = n_base + nf * 8 + qc;
                *reinterpret_cast<float2*>(&s_pre[row * PPAD + col]) =
                    make_float2(acc[mf][nf][0], acc[mf][nf][1]);
                *reinterpret_cast<float2*>(&s_pre[(row + 8) * PPAD + col]) =
                    make_float2(acc[mf][nf][2], acc[mf][nf][3]);
            }
    }
    __syncthreads();

    // ---- fused LIF scan: 128 threads = 128 columns ----
    {
        const int c = tid;
        float vmem = 0.f;
        const size_t ostride = (size_t)4096 * ldo;
        const size_t obase = (size_t)bn * ldo + ocol0 + c;
        const size_t gbase = (size_t)bn * 128 + c;
#pragma unroll 1
        for (int t = 0; t < 64; t++) {
            float p = s_pre[t * PPAD + c];
            vmem = __fadd_rn(vmem, __fmul_rn(__fsub_rn(p, vmem), 0.5f));
            float spk = (vmem >= 1.0f) ? 1.0f : 0.0f;
            if (vmem >= 1.0f) vmem = 0.0f;
            size_t oi = obase + (size_t)t * ostride;
            if (MODE == 0) {
                ((__half*)outp)[oi] = __float2half_rn(spk);
            } else {
                float g = gx[gbase + (size_t)t * (size_t)BND];
                float val = __fmul_rn(g, __fsub_rn(1.0f, spk));
                ((float*)outp)[oi] = val;
                if (MODE == 1) {
                    __half hi = __float2half_rn(val);
                    float r1 = __fsub_rn(val, __half2float(hi));
                    so0[oi] = hi;
                    so1[oi] = __float2half_rn(r1);
                }
            }
        }
    }
}

// =====================================================================
// Attention via tensor cores (exact fp16 in/out), emits o splits.
// =====================================================================
constexpr int ATT_Q = 0, ATT_K = 16384, ATT_V = 32768, ATT_AT = 49152;
constexpr int SATT = 65536;

__global__ void __launch_bounds__(256) k_attn3(const __half* __restrict__ q,
                                               const __half* __restrict__ k,
                                               const __half* __restrict__ v,
                                               __half* __restrict__ so0,
                                               __half* __restrict__ so1) {
    extern __shared__ __align__(16) char sm_raw[];
    const uint32_t sbase = smem_u32(sm_raw);
    const size_t base = (size_t)blockIdx.x * 8192;
    const int tid = threadIdx.x;
    const int wid = tid >> 5, lane = tid & 31;

    for (int u = tid; u < 4096; u += 256) {
        int n = u >> 6;
        int d = (u & 63) * 2;
        int h = d >> 6, dd = d & 63;
        uint32_t qp = *reinterpret_cast<const uint32_t*>(&q[base + 2 * u]);
        uint32_t kp = *reinterpret_cast<const uint32_t*>(&k[base + 2 * u]);
        uint32_t vp = *reinterpret_cast<const uint32_t*>(&v[base + 2 * u]);
        uint32_t off = sw128((n << 7) + (dd << 1));
        *reinterpret_cast<uint32_t*>(sm_raw + ATT_Q + h * 8192 + off) = qp;
        *reinterpret_cast<uint32_t*>(sm_raw + ATT_K + h * 8192 + off) = kp;
        *reinterpret_cast<uint16_t*>(sm_raw + ATT_V + h * 8192 +
            sw128((dd << 7) + (n << 1))) = (uint16_t)(vp & 0xffffu);
        *reinterpret_cast<uint16_t*>(sm_raw + ATT_V + h * 8192 +
            sw128(((dd + 1) << 7) + (n << 1))) = (uint16_t)(vp >> 16);
    }
    __syncthreads();

    const int sub = lane >> 3, lr = lane & 7;
    const int arow_off = (sub & 1) * 8 + lr;
    const int akc = (sub >> 1) * 8;
    const int brow_off = (sub >> 1) * 8 + lr;
    const int bkc = (sub & 1) * 8;
    const int qr = lane >> 2, qc = (lane & 3) * 2;

    float acc[8][4];

    {   // phase 1: attn = 0.125 * q.kT
        const int h = wid & 1;
        const int n_b = (wid >> 1) * 16;
        uint32_t Abase = sbase + ATT_Q + h * 8192;
        uint32_t Bbase = sbase + ATT_K + h * 8192;
#pragma unroll
        for (int j = 0; j < 8; j++)
#pragma unroll
            for (int e = 0; e < 4; e++) acc[j][e] = 0.f;
#pragma unroll
        for (int ks = 0; ks < 4; ks++) {
            int k0 = ks * 16;
            uint32_t afr[4];
            ldsm4(afr, Abase + sw128(((n_b + arow_off) << 7) + (k0 + akc) * 2));
#pragma unroll
            for (int mf2 = 0; mf2 < 4; mf2++) {
                uint32_t bfr[4];
                ldsm4(bfr, Bbase + sw128(((mf2 * 16 + brow_off) << 7) + (k0 + bkc) * 2));
                mma16816(acc[mf2 * 2 + 0], afr, bfr[0], bfr[1]);
                mma16816(acc[mf2 * 2 + 1], afr, bfr[2], bfr[3]);
            }
        }
        uint32_t Obase = (uint32_t)(ATT_AT + h * 8192);
#pragma unroll
        for (int j = 0; j < 8; j++) {
            int m_col = j * 8 + qc;
            int r0 = n_b + qr;
            *reinterpret_cast<uint32_t*>(sm_raw + Obase +
                sw128((r0 << 7) + m_col * 2)) = h2x(acc[j][0] * 0.125f, acc[j][1] * 0.125f);
            *reinterpret_cast<uint32_t*>(sm_raw + Obase +
                sw128(((r0 + 8) << 7) + m_col * 2)) = h2x(acc[j][2] * 0.125f, acc[j][3] * 0.125f);
        }
    }
    __syncthreads();

    {   // phase 2: o = attn . vT, emit exact 2-way fp16 splits
        const int h = wid >> 2;
        const int n_b = (wid & 3) * 16;
        uint32_t Abase = sbase + ATT_AT + h * 8192;
        uint32_t Bbase = sbase + ATT_V + h * 8192;
#pragma unroll
        for (int j = 0; j < 8; j++)
#pragma unroll
            for (int e = 0; e < 4; e++) acc[j][e] = 0.f;
#pragma unroll
        for (int ks = 0; ks < 4; ks++) {
            int k0 = ks * 16;
            uint32_t afr[4];
            ldsm4(afr, Abase + sw128(((n_b + arow_off) << 7) + (k0 + akc) * 2));
#pragma unroll
            for (int df = 0; df < 4; df++) {
                uint32_t bfr[4];
                ldsm4(bfr, Bbase + sw128(((df * 16 + brow_off) << 7) + (k0 + bkc) * 2));
                mma16816(acc[df * 2 + 0], afr, bfr[0], bfr[1]);
                mma16816(acc[df * 2 + 1], afr, bfr[2], bfr[3]);
            }
        }
#pragma unroll
        for (int j = 0; j < 8; j++) {
            int d_col = h * 64 + j * 8 + qc;
#pragma unroll
            for (int half = 0; half < 2; half++) {
                int r0 = n_b + qr + half * 8;
                float f0 = acc[j][half * 2 + 0], f1 = acc[j][half * 2 + 1];
                float h0 = __half2float(__float2half_rn(f0));
                float h1v = __half2float(__float2half_rn(f1));
                size_t oi = base + (size_t)r0 * 128 + d_col;
                *reinterpret_cast<uint32_t*>(&so0[oi]) = h2x(f0, f1);
                *reinterpret_cast<uint32_t*>(&so1[oi]) =
                    h2x(__fsub_rn(f0, h0), __fsub_rn(f1, h1v));
            }
        }
    }
}

// =====================================================================
// Host side
// =====================================================================
extern "C" void kernel_launch(void* const* d_in, const int* in_sizes, int n_in,
                              void* d_out, int out_size) {
    const float* x  = (const float*)d_in[0];
    const float* mx = (const float*)d_in[1];
    const float* Wq = (const float*)d_in[2];
    const float* Wk = (const float*)d_in[3];
    const float* Wv = (const float*)d_in[4];
    const float* Wo = (const float*)d_in[5];
    const float* W1 = (const float*)d_in[6];
    const float* W2 = (const float*)d_in[7];
    float* out = (float*)d_out;

    void *p_xs, *p_ms, *p_os, *p_xgs, *p_xg, *p_q, *p_k, *p_v, *p_h1, *p_wsp;
    cudaGetSymbolAddress(&p_xs, g_xs);
    cudaGetSymbolAddress(&p_ms, g_ms);
    cudaGetSymbolAddress(&p_os, g_os);
    cudaGetSymbolAddress(&p_xgs, g_xgs);
    cudaGetSymbolAddress(&p_xg, g_xg);
    cudaGetSymbolAddress(&p_q, g_q);
    cudaGetSymbolAddress(&p_k, g_k);
    cudaGetSymbolAddress(&p_v, g_v);
    cudaGetSymbolAddress(&p_h1, g_h1);
    cudaGetSymbolAddress(&p_wsp, g_wsp);
    __half* xs = (__half*)p_xs;
    __half* ms = (__half*)p_ms;
    __half* os = (__half*)p_os;
    __half* xgs = (__half*)p_xgs;
    __half* wsp = (__half*)p_wsp;
    const size_t WSTRIDE = 2 * 128 * 256;

    cudaFuncSetAttribute(k_mmag<1, 0, 2, 1>, cudaFuncAttributeMaxDynamicSharedMemorySize, SGEMM);
    cudaFuncSetAttribute(k_mmag<1, 0, 2, 2>, cudaFuncAttributeMaxDynamicSharedMemorySize, SGEMM);
    cudaFuncSetAttribute(k_mmag<1, 1, 2, 1>, cudaFuncAttributeMaxDynamicSharedMemorySize, SGEMM);
    cudaFuncSetAttribute(k_mmag<2, 2, 1, 1>, cudaFuncAttributeMaxDynamicSharedMemorySize, SGEMM);
    cudaFuncSetAttribute(k_attn3, cudaFuncAttributeMaxDynamicSharedMemorySize, SATT);

    k_xsplit<<<2048, 256>>>(x);                                             // 1
    k_wsplit_all<<<512, 256>>>(Wq, Wk, Wv, Wo, W1, W2);                     // 2
    k_dct<<<64, 64>>>();                                                    // 3
    // q = LIF(x @ Wq)   <- launch #4: profiled
    k_mmag<1, 0, 2, 1><<<4096, 128, SGEMM>>>(xs, TOT, wsp + 0 * WSTRIDE, nullptr,
        p_q, nullptr, 128, 0, nullptr, nullptr, nullptr);                   // 4
    k_pack<<<32, 64>>>();                                                   // 5
    k_mix<<<4096, 256>>>(x, mx);                                            // 6
    // k,v = LIF(mlp @ Wk/Wv)  fused
    k_mmag<1, 0, 2, 2><<<8192, 128, SGEMM>>>(ms, TOT, wsp + 1 * WSTRIDE,
        wsp + 2 * WSTRIDE, p_k, p_v, 128, 0, nullptr, nullptr, nullptr);    // 7
    k_attn3<<<4096, 256, SATT>>>((const __half*)p_q, (const __half*)p_k,
        (const __half*)p_v, os, os + TOT);                                  // 8
    // xg = x * (1 - LIF(o @ Wo))
    k_mmag<1, 1, 2, 1><<<4096, 128, SGEMM>>>(os, TOT, wsp + 3 * WSTRIDE, nullptr,
        p_xg, nullptr, 128, 0, x, xgs, xgs + TOT);                          // 9
    // h1 = LIF(xg @ W1) (both N-halves fused)
    k_mmag<1, 0, 2, 2><<<8192, 128, SGEMM>>>(xgs, TOT, wsp + 4 * WSTRIDE,
        wsp + 5 * WSTRIDE, p_h1, p_h1, 256, 128, nullptr, nullptr, nullptr);// 10
    // out = xg * (1 - LIF(h1 @ W2))  (binary h1 -> 1 split, K=256)
    k_mmag<2, 2, 1, 1><<<4096, 128, SGEMM>>>((const __half*)p_h1, 0,
        wsp + 6 * WSTRIDE, nullptr, out, nullptr, 128, 0, (const float*)p_xg,
        nullptr, nullptr);                                                  // 11
}